// round 6
// baseline (speedup 1.0000x reference)
#include <cuda_runtime.h>

#define N_PART 512
#define NK 32
#define NT 10
#define NB 8
#define EPSF 1e-6f

// Per-k folded constants: {mu_k, -ig2_k, w_eff_k, -2*ig2_k*w_eff_k}
__device__ float4 g_cK[NK];
__device__ float g_C;

__global__ void prep_kernel(const float* __restrict__ t,
                            const float* __restrict__ mus,
                            const float* __restrict__ nlg,
                            const float* __restrict__ mus_t,
                            const float* __restrict__ nlg_t,
                            const float* __restrict__ W,
                            const float* __restrict__ bias,
                            const float* __restrict__ imp,
                            float* __restrict__ div_out) {
    __shared__ float strbf[NT];
    int k = threadIdx.x;
    if (k == 0) {
        float tt = t[0];
        float rb[NT];
        float s = 0.f;
        for (int i = 0; i < NT; i++) {
            float g = expf(nlg_t[i]);
            float ig2 = g * g;
            float diff = tt - mus_t[i];
            float e = expf(-diff * diff * ig2);
            rb[i] = e;
            s += e;
        }
        float inv = 1.f / (EPSF + s);
        for (int i = 0; i < NT; i++) strbf[i] = rb[i] * inv;
    }
    __syncthreads();
    // k in [0,32): effective weight folded over time kernels
    float w = 0.f;
    for (int ti = 0; ti < NT; ti++) w += W[k * NT + ti] * strbf[ti];
    float g = expf(nlg[k]);
    float ig2 = g * g;
    g_cK[k] = make_float4(mus[k], -ig2, w, -2.f * ig2 * w);
    float cp = imp[k] * imp[k] * w;
    #pragma unroll
    for (int o = 16; o > 0; o >>= 1) cp += __shfl_down_sync(0xffffffffu, cp, o);
    if (k == 0) {
        float bb = 0.f;
        for (int ti = 0; ti < NT; ti++) bb += bias[ti] * strbf[ti];
        g_C = bb + cp;
    }
    if (k < NB) div_out[k] = 0.f;
}

__global__ __launch_bounds__(256) void force_kernel(const float* __restrict__ x,
                                                    float* __restrict__ f_out,
                                                    float* __restrict__ div_out) {
    __shared__ float sx[N_PART * 3];
    __shared__ float4 sc[NK];
    const int b = blockIdx.y;
    const int tid = threadIdx.x;

    for (int idx = tid; idx < N_PART * 3; idx += 256)
        sx[idx] = x[b * N_PART * 3 + idx];
    if (tid < NK) sc[tid] = g_cK[tid];
    __syncthreads();

    const float C = g_C;
    const int warp = tid >> 5;
    const int lane = tid & 31;
    const int i = blockIdx.x * 8 + warp;

    const float xi0 = sx[i * 3 + 0];
    const float xi1 = sx[i * 3 + 1];
    const float xi2 = sx[i * 3 + 2];

    float fx = 0.f, fy = 0.f, fz = 0.f, dv = 0.f;

    #pragma unroll 1
    for (int jj = 0; jj < 16; jj++) {
        const int j = lane + jj * 32;
        const float dx = xi0 - sx[j * 3 + 0];
        const float dy = xi1 - sx[j * 3 + 1];
        const float dz = xi2 - sx[j * 3 + 2];
        const float d2 = fmaf(dx, dx, fmaf(dy, dy, fmaf(dz, dz, EPSF)));
        const float d = sqrtf(d2);

        float srbf = 0.f, s1 = 0.f, sd = 0.f, s2 = 0.f;
        #pragma unroll
        for (int k = 0; k < NK; k++) {
            const float4 c = sc[k];
            const float diff = d - c.x;          // d - mu
            const float e = __expf(diff * diff * c.y);  // exp(-diff^2 * ig2)
            srbf += e;
            s1 = fmaf(e, c.z, s1);               // sum e * w
            const float p = diff * e;
            sd = fmaf(p, c.y, sd);               // (1/2) * sum drbf
            s2 = fmaf(p, c.w, s2);               // sum drbf * w
        }
        const float rinv = __fdividef(1.f, EPSF + srbf);
        const float q = s1 * rinv;               // kernels . w
        float fm = q + C;                        // force magnitude (scalar over T)
        float dfm = (s2 - q * (2.f * sd)) * rinv;
        const float m = (j != i) ? 1.f : 0.f;
        fm *= m;
        dfm *= m;
        fx = fmaf(dx, fm, fx);
        fy = fmaf(dy, fm, fy);
        fz = fmaf(dz, fm, fz);
        dv += fmaf(d, dfm, 3.f * fm);
    }

    #pragma unroll
    for (int o = 16; o > 0; o >>= 1) {
        fx += __shfl_down_sync(0xffffffffu, fx, o);
        fy += __shfl_down_sync(0xffffffffu, fy, o);
        fz += __shfl_down_sync(0xffffffffu, fz, o);
        dv += __shfl_down_sync(0xffffffffu, dv, o);
    }
    if (lane == 0) {
        f_out[b * N_PART * 3 + i * 3 + 0] = fx;
        f_out[b * N_PART * 3 + i * 3 + 1] = fy;
        f_out[b * N_PART * 3 + i * 3 + 2] = fz;
        atomicAdd(&div_out[b], -dv);   // reference returns -divergence
    }
}

extern "C" void kernel_launch(void* const* d_in, const int* in_sizes, int n_in,
                              void* d_out, int out_size) {
    const float* t     = (const float*)d_in[0];
    const float* x     = (const float*)d_in[1];
    const float* mus   = (const float*)d_in[2];
    const float* nlg   = (const float*)d_in[3];
    const float* mus_t = (const float*)d_in[4];
    const float* nlg_t = (const float*)d_in[5];
    const float* W     = (const float*)d_in[6];
    const float* bias  = (const float*)d_in[7];
    const float* imp   = (const float*)d_in[8];

    float* out = (float*)d_out;
    float* div_out = out + (out_size - NB);   // forces first, then -divergence per batch

    prep_kernel<<<1, 32>>>(t, mus, nlg, mus_t, nlg_t, W, bias, imp, div_out);
    force_kernel<<<dim3(N_PART / 8, NB), 256>>>(x, out, div_out);
}

// round 7
// speedup vs baseline: 1.2402x; 1.2402x over previous
#include <cuda_runtime.h>

#define N_PART 512
#define NK 32
#define NT 10
#define NB 8
#define EPSF 1e-6f
#define LOG2E 1.4426950408889634f
#define TWO_LN2 1.3862943611198906f

// Per-k folded constants: {mu_k, -ig2_k*log2e, w_eff_k, -2*ig2_k*w_eff_k}
__device__ float4 g_cK[NK];
__device__ float g_C;

__device__ __forceinline__ float ex2f(float x) {
    float r;
    asm("ex2.approx.f32 %0, %1;" : "=f"(r) : "f"(x));
    return r;
}

__global__ void prep_kernel(const float* __restrict__ t,
                            const float* __restrict__ mus,
                            const float* __restrict__ nlg,
                            const float* __restrict__ mus_t,
                            const float* __restrict__ nlg_t,
                            const float* __restrict__ W,
                            const float* __restrict__ bias,
                            const float* __restrict__ imp,
                            float* __restrict__ div_out) {
    __shared__ float strbf[NT];
    int k = threadIdx.x;
    if (k == 0) {
        float tt = t[0];
        float rb[NT];
        float s = 0.f;
        for (int i = 0; i < NT; i++) {
            float g = expf(nlg_t[i]);
            float ig2 = g * g;
            float diff = tt - mus_t[i];
            float e = expf(-diff * diff * ig2);
            rb[i] = e;
            s += e;
        }
        float inv = 1.f / (EPSF + s);
        for (int i = 0; i < NT; i++) strbf[i] = rb[i] * inv;
    }
    __syncthreads();
    // k in [0,32): effective weight folded over time kernels
    float w = 0.f;
    for (int ti = 0; ti < NT; ti++) w += W[k * NT + ti] * strbf[ti];
    float g = expf(nlg[k]);
    float ig2 = g * g;
    // y component pre-scaled by log2e so the inner loop can use ex2 directly
    g_cK[k] = make_float4(mus[k], -ig2 * LOG2E, w, -2.f * ig2 * w);
    float cp = imp[k] * imp[k] * w;
    #pragma unroll
    for (int o = 16; o > 0; o >>= 1) cp += __shfl_down_sync(0xffffffffu, cp, o);
    if (k == 0) {
        float bb = 0.f;
        for (int ti = 0; ti < NT; ti++) bb += bias[ti] * strbf[ti];
        g_C = bb + cp;
    }
    if (k < NB) div_out[k] = 0.f;
}

__global__ __launch_bounds__(128, 6) void force_kernel(const float* __restrict__ x,
                                                       float* __restrict__ f_out,
                                                       float* __restrict__ div_out) {
    __shared__ float sx[N_PART * 3];
    __shared__ float4 sc[NK];
    const int b = blockIdx.y;
    const int tid = threadIdx.x;

    for (int idx = tid; idx < N_PART * 3; idx += 128)
        sx[idx] = x[b * N_PART * 3 + idx];
    if (tid < NK) sc[tid] = g_cK[tid];
    __syncthreads();

    const float C = g_C;
    const int warp = tid >> 5;
    const int lane = tid & 31;
    const int i = blockIdx.x * 4 + warp;

    const float xi0 = sx[i * 3 + 0];
    const float xi1 = sx[i * 3 + 1];
    const float xi2 = sx[i * 3 + 2];

    float fx = 0.f, fy = 0.f, fz = 0.f, dv = 0.f;

    #pragma unroll 1
    for (int jj = 0; jj < 16; jj++) {
        const int j = lane + jj * 32;
        const float dx = xi0 - sx[j * 3 + 0];
        const float dy = xi1 - sx[j * 3 + 1];
        const float dz = xi2 - sx[j * 3 + 2];
        const float d2 = fmaf(dx, dx, fmaf(dy, dy, fmaf(dz, dz, EPSF)));
        const float d = sqrtf(d2);

        float srbf = 0.f, s1 = 0.f, sd = 0.f, s2 = 0.f;
        #pragma unroll 8
        for (int k = 0; k < NK; k++) {
            const float4 c = sc[k];
            const float diff = d - c.x;            // d - mu
            const float e = ex2f(diff * diff * c.y); // exp(-diff^2*ig2) via ex2
            srbf += e;
            s1 = fmaf(e, c.z, s1);                 // sum e * w
            const float p = diff * e;
            sd = fmaf(p, c.y, sd);                 // log2e * (1/2) * sum drbf
            s2 = fmaf(p, c.w, s2);                 // sum drbf * w
        }
        const float rinv = __fdividef(1.f, EPSF + srbf);
        const float q = s1 * rinv;                 // kernels . w
        float fm = q + C;                          // force magnitude (scalar over T)
        // sd carries an extra log2e factor; 2*sd_true = TWO_LN2 * sd
        float dfm = (s2 - q * (TWO_LN2 * sd)) * rinv;
        const float m = (j != i) ? 1.f : 0.f;
        fm *= m;
        dfm *= m;
        fx = fmaf(dx, fm, fx);
        fy = fmaf(dy, fm, fy);
        fz = fmaf(dz, fm, fz);
        dv += fmaf(d, dfm, 3.f * fm);
    }

    #pragma unroll
    for (int o = 16; o > 0; o >>= 1) {
        fx += __shfl_down_sync(0xffffffffu, fx, o);
        fy += __shfl_down_sync(0xffffffffu, fy, o);
        fz += __shfl_down_sync(0xffffffffu, fz, o);
        dv += __shfl_down_sync(0xffffffffu, dv, o);
    }
    if (lane == 0) {
        f_out[b * N_PART * 3 + i * 3 + 0] = fx;
        f_out[b * N_PART * 3 + i * 3 + 1] = fy;
        f_out[b * N_PART * 3 + i * 3 + 2] = fz;
        atomicAdd(&div_out[b], -dv);   // reference returns -divergence
    }
}

extern "C" void kernel_launch(void* const* d_in, const int* in_sizes, int n_in,
                              void* d_out, int out_size) {
    const float* t     = (const float*)d_in[0];
    const float* x     = (const float*)d_in[1];
    const float* mus   = (const float*)d_in[2];
    const float* nlg   = (const float*)d_in[3];
    const float* mus_t = (const float*)d_in[4];
    const float* nlg_t = (const float*)d_in[5];
    const float* W     = (const float*)d_in[6];
    const float* bias  = (const float*)d_in[7];
    const float* imp   = (const float*)d_in[8];

    float* out = (float*)d_out;
    float* div_out = out + (out_size - NB);   // forces first, then -divergence per batch

    prep_kernel<<<1, 32>>>(t, mus, nlg, mus_t, nlg_t, W, bias, imp, div_out);
    force_kernel<<<dim3(N_PART / 4, NB), 128>>>(x, out, div_out);
}